// round 17
// baseline (speedup 1.0000x reference)
#include <cuda_runtime.h>

// HighOrderActivationA: B=8192, G=256, arity=4, O=16, fp32.
// out[b, g*16+o] = sum_k coef[b,g,k] * params[g, idx[b,g,k], o]
//
// R14: phase-split. Phase A: every lane argsorts its OWN (b,g) item
// (32 items per warp pass instead of 8 -> sort issue cost /4), producing
// coefs c0..c3 and the three gather masks packed into one int. Phase B:
// 4 rounds in the proven (jq,gl) layout (conflict-free LDS gathers,
// 512B-contiguous STG.128, broadcast LDG), with coefs/masks fetched via
// __shfl_sync. FMAs use packed fma.rn.f32x2 (2 lanes of fp32 per instr).

#define G_TOT   256
#define ARITY   4
#define O_DIM   16
#define NROWS   16
#define GPB     8
#define THREADS 256
#define WARPS   8
#define BPT     8                  // b per warp (2 super-iters x 4)
#define BPB     (WARPS * BPT)      // 64 b per block
#define ROWPITCH (GPB * O_DIM)     // 128 floats per table row

#define CSWAP(va, vb, ia, ib)                 \
    {                                          \
        bool _sw = (va) > (vb);                \
        float _tv = _sw ? (vb) : (va);         \
        (vb) = _sw ? (va) : (vb);              \
        (va) = _tv;                            \
        int _ti = _sw ? (ib) : (ia);           \
        (ib) = _sw ? (ia) : (ib);              \
        (ia) = _ti;                            \
    }

__device__ __forceinline__ unsigned long long pk2(float lo, float hi) {
    unsigned long long r;
    asm("mov.b64 %0, {%1, %2};" : "=l"(r) : "f"(lo), "f"(hi));
    return r;
}
__device__ __forceinline__ unsigned long long fma2(unsigned long long a,
                                                   unsigned long long b,
                                                   unsigned long long c) {
    unsigned long long d;
    asm("fma.rn.f32x2 %0, %1, %2, %3;" : "=l"(d) : "l"(a), "l"(b), "l"(c));
    return d;
}
__device__ __forceinline__ unsigned long long mul2(unsigned long long a,
                                                   unsigned long long b) {
    unsigned long long d;
    asm("mul.rn.f32x2 %0, %1, %2;" : "=l"(d) : "l"(a), "l"(b));
    return d;
}
__device__ __forceinline__ void upk2(unsigned long long v, float& lo, float& hi) {
    asm("mov.b64 {%0, %1}, %2;" : "=f"(lo), "=f"(hi) : "l"(v));
}

__global__ __launch_bounds__(THREADS, 5)
void hoa_kernel(const float* __restrict__ X,
                const float* __restrict__ params,
                float* __restrict__ out,
                int B)
{
    // P[row][gl][o] : 16*8*16 floats = 8 KB, natural layout (conflict-free
    // under the (jq,gl) lane mapping).
    __shared__ __align__(16) float P[NROWS * ROWPITCH];

    const int tid  = threadIdx.x;
    const int lane = tid & 31;
    const int wid  = tid >> 5;
    const int jq   = lane & 3;          // o-quarter (phase B)
    const int gl   = (lane >> 2) & 7;   // group     (phase B)
    const int ga   = lane & 7;          // group     (phase A)
    const int ba   = lane >> 3;         // b offset  (phase A), 0..3
    const int g_base = blockIdx.x * GPB;

    // Cooperative table load: params[g][row][o] -> smem [row][gl][o].
    {
        const float4* __restrict__ Pg4 =
            (const float4*)(params + (long)g_base * (NROWS * O_DIM));
        float4* S4 = (float4*)P;
        #pragma unroll
        for (int i = tid; i < GPB * NROWS * 4; i += THREADS) {
            int oq  = i & 3;
            int row = (i >> 2) & 15;
            int gg  = i >> 6;
            S4[row * (ROWPITCH / 4) + gg * 4 + oq] = Pg4[i];
        }
    }
    __syncthreads();

    const float4* __restrict__ X4 = (const float4*)X;   // [B, G_TOT] float4s
    float4* __restrict__ Out4 = (float4*)out;           // [B, G_TOT*4] float4s

    const float4* Ps = (const float4*)P + gl * 4 + jq;

    // Row 15 (constant suffix mask) cached packed: 2 regs.
    float4 p15 = Ps[15 * (ROWPITCH / 4)];
    const unsigned long long a0lo = pk2(p15.x, p15.y);
    const unsigned long long a0hi = pk2(p15.z, p15.w);

    const long wbase = (long)blockIdx.y * BPB + wid * BPT;

    #pragma unroll
    for (int s = 0; s < BPT / 4; s++) {
        long b0 = wbase + s * 4;

        // ---- Phase A: each lane sorts its own item (b0+ba, g_base+ga) ----
        long bA = b0 + ba;
        if (bA >= B) bA = B - 1;        // clamp (result unused if OOB)
        float4 x = X4[bA * G_TOT + g_base + ga];

        float v0 = x.x, v1 = x.y, v2 = x.z, v3 = x.w;
        int i0 = 0, i1 = 1, i2 = 2, i3 = 3;
        CSWAP(v0, v1, i0, i1);
        CSWAP(v2, v3, i2, i3);
        CSWAP(v0, v2, i0, i2);
        CSWAP(v1, v3, i1, i3);
        CSWAP(v1, v2, i1, i2);

        float c0 = v0;
        float c1 = v1 - v0;
        float c2 = v2 - v1;
        float c3 = v3 - v2;

        int m3 = 1 << i3;
        int m2 = m3 + (1 << i2);
        int m1 = m2 + (1 << i1);
        int mpack = m1 | (m2 << 4) | (m3 << 8);

        // ---- Phase B: 4 rounds, (jq,gl) layout, coefs via shuffle ----
        #pragma unroll
        for (int r = 0; r < 4; r++) {
            long b = b0 + r;
            if (b >= B) break;          // warp-uniform

            int src = r * 8 + gl;
            float c0r = __shfl_sync(0xffffffffu, c0, src);
            float c1r = __shfl_sync(0xffffffffu, c1, src);
            float c2r = __shfl_sync(0xffffffffu, c2, src);
            float c3r = __shfl_sync(0xffffffffu, c3, src);
            int   mpr = __shfl_sync(0xffffffffu, mpack, src);

            int rm1 = mpr & 15;
            int rm2 = (mpr >> 4) & 15;
            int rm3 = (mpr >> 8) & 15;

            float4 a1 = Ps[rm1 * (ROWPITCH / 4)];
            float4 a2 = Ps[rm2 * (ROWPITCH / 4)];
            float4 a3 = Ps[rm3 * (ROWPITCH / 4)];

            unsigned long long cc0 = pk2(c0r, c0r);
            unsigned long long cc1 = pk2(c1r, c1r);
            unsigned long long cc2 = pk2(c2r, c2r);
            unsigned long long cc3 = pk2(c3r, c3r);

            unsigned long long lo = mul2(cc3, pk2(a3.x, a3.y));
            lo = fma2(cc2, pk2(a2.x, a2.y), lo);
            lo = fma2(cc1, pk2(a1.x, a1.y), lo);
            lo = fma2(cc0, a0lo, lo);

            unsigned long long hi = mul2(cc3, pk2(a3.z, a3.w));
            hi = fma2(cc2, pk2(a2.z, a2.w), hi);
            hi = fma2(cc1, pk2(a1.z, a1.w), hi);
            hi = fma2(cc0, a0hi, hi);

            float4 acc;
            upk2(lo, acc.x, acc.y);
            upk2(hi, acc.z, acc.w);

            // Warp store: lanes (jq,gl) cover one contiguous 512B span.
            Out4[b * (G_TOT * 4) + (g_base + gl) * 4 + jq] = acc;
        }
    }
}

extern "C" void kernel_launch(void* const* d_in, const int* in_sizes, int n_in,
                              void* d_out, int out_size)
{
    const float* X      = (const float*)d_in[0];   // [B, G*4]
    const float* params = (const float*)d_in[1];   // [G, 16, 16]
    float* out          = (float*)d_out;           // [B, G*16]

    int B = in_sizes[0] / (G_TOT * ARITY);

    dim3 block(THREADS);
    dim3 grid(G_TOT / GPB, (B + BPB - 1) / BPB);
    hoa_kernel<<<grid, block>>>(X, params, out, B);
}